// round 15
// baseline (speedup 1.0000x reference)
#include <cuda_runtime.h>
#include <cuda_bf16.h>
#include <cstdint>

// Problem constants
#define BB 2
#define LL 2048
#define DD 1024
#define NH 16
#define HD 64
#define MM (BB*LL)      // 4096
#define N3 (3*DD)       // 3072
#define KK DD           // 1024

typedef unsigned long long u64;
typedef unsigned int u32;

// ---- tf32 mma.sync helpers ----
__device__ __forceinline__ u32 f2tf32(float f) {
    u32 r; asm("cvt.rna.tf32.f32 %0, %1;" : "=r"(r) : "f"(f)); return r;
}
__device__ __forceinline__ void mma_tf32(float& d0, float& d1, float& d2, float& d3,
                                         u32 a0, u32 a1, u32 a2, u32 a3,
                                         u32 b0, u32 b1) {
    asm volatile(
        "mma.sync.aligned.m16n8k8.row.col.f32.tf32.tf32.f32 "
        "{%0,%1,%2,%3}, {%4,%5,%6,%7}, {%8,%9}, {%0,%1,%2,%3};"
        : "+f"(d0), "+f"(d1), "+f"(d2), "+f"(d3)
        : "r"(a0), "r"(a1), "r"(a2), "r"(a3), "r"(b0), "r"(b1));
}
__device__ __forceinline__ float ex2(float x) {
    float y; asm("ex2.approx.f32 %0, %1;" : "=f"(y) : "f"(x)); return y;
}
__device__ __forceinline__ u32 smem_u32(const void* p) {
    u32 a;
    asm("{ .reg .u64 t; cvta.to.shared.u64 t, %1; cvt.u32.u64 %0, t; }" : "=r"(a) : "l"(p));
    return a;
}
__device__ __forceinline__ void ldsm_x4(u32& r0, u32& r1, u32& r2, u32& r3, u32 addr) {
    asm volatile("ldmatrix.sync.aligned.m8n8.x4.shared.b16 {%0,%1,%2,%3}, [%4];"
                 : "=r"(r0), "=r"(r1), "=r"(r2), "=r"(r3) : "r"(addr));
}
__device__ __forceinline__ void cpa16(u32 dst, const void* src) {
    asm volatile("cp.async.cg.shared.global [%0], [%1], 16;" :: "r"(dst), "l"(src) : "memory");
}
#define CP_COMMIT() asm volatile("cp.async.commit_group;" ::: "memory")
#define CP_WAIT0()  asm volatile("cp.async.wait_group 0;" ::: "memory")
#define CP_WAIT1()  asm volatile("cp.async.wait_group 1;" ::: "memory")

// Scratch: qkv [4096,3072] f32 (tf32-rounded values); pre-rounded x and W.
__device__ float g_qkv[(size_t)MM * N3];
__device__ float g_xc[(size_t)MM * KK];
__device__ float g_wc[(size_t)N3 * KK];

// ---------------------------------------------------------------------------
// Kernel 0: pre-pass — rna-round x and W to tf32 values (stored as f32 bits).
// ---------------------------------------------------------------------------
__global__ void cvt_prepass(const float* __restrict__ x, const float* __restrict__ W,
                            float* __restrict__ xc, float* __restrict__ wc)
{
    const size_t nx4 = (size_t)MM * KK / 4;
    const size_t nw4 = (size_t)N3 * KK / 4;
    size_t i = (size_t)blockIdx.x * blockDim.x + threadIdx.x;
    if (i < nx4) {
        float4 v = ((const float4*)x)[i];
        ((uint4*)xc)[i] = make_uint4(f2tf32(v.x), f2tf32(v.y), f2tf32(v.z), f2tf32(v.w));
    } else if (i < nx4 + nw4) {
        size_t j = i - nx4;
        float4 v = ((const float4*)W)[j];
        ((uint4*)wc)[j] = make_uint4(f2tf32(v.x), f2tf32(v.y), f2tf32(v.z), f2tf32(v.w));
    }
}

// ---------------------------------------------------------------------------
// Kernel 1: QKV GEMM, mma.sync tf32, 3-stage cp.async pipeline, K-chunk 16
// (half the syncs of chunk-8). smem row stride 20 floats = 80 B: 16B-aligned,
// LDSM 16B-group (5r + c) mod 8 distinct. 61 KB smem -> 2 CTAs/SM.
// ---------------------------------------------------------------------------
#define GST 20

__global__ __launch_bounds__(256, 2) void qkv_gemm_mma(
    const float* __restrict__ x,     // pre-rounded [MM, KK]
    const float* __restrict__ W,     // pre-rounded [N3, KK]
    const float* __restrict__ bias,
    float* __restrict__ C)           // [MM, N3] (tf32-rounded values)
{
    __shared__ u32 sX[3 * 128 * GST];
    __shared__ u32 sW[3 * 128 * GST];
    __shared__ float sBias[128];

    const int bm = blockIdx.y * 128;
    const int bn = blockIdx.x * 128;
    const int tid  = threadIdx.x;
    const int wid  = tid >> 5;
    const int lane = tid & 31;
    const int wm = (wid >> 2) * 64;
    const int wn = (wid & 3) * 32;
    const int lr = lane >> 2;
    const int lc = lane & 3;

    // chunk load: 128 rows x 16 k = 512 f4 per matrix; 2 per thread each
    const int l_row = tid >> 1;      // 0..127
    const int l_f4  = tid & 1;       // f4 = l_f4 + 2i, i in {0,1}

    const u32 sXa = smem_u32(sX);
    const u32 sWa = smem_u32(sW);
    const u32 SSZ = 128 * GST * 4;   // bytes per stage
    const float* xsrc = x + (size_t)(bm + l_row) * KK;
    const float* wsrc = W + (size_t)(bn + l_row) * KK;

    const int lm  = lane >> 3;
    const int lrw = lane & 7;
    const int a_row = (lm & 1) * 8 + lrw;
    const int a_col = (lm >> 1) * 4;
    const int b_nt  = lm >> 1;
    const int b_col = (lm & 1) * 4;

    float d[4][4][4];
#pragma unroll
    for (int mt = 0; mt < 4; mt++)
#pragma unroll
        for (int nt = 0; nt < 4; nt++)
#pragma unroll
            for (int r = 0; r < 4; r++) d[mt][nt][r] = 0.f;

    if (tid < 128) sBias[tid] = bias[bn + tid];

    // prologue: stages 0,1 in flight
#pragma unroll
    for (int s = 0; s < 2; s++) {
#pragma unroll
        for (int i = 0; i < 2; i++) {
            int f4 = l_f4 + i * 2;
            u32 off = (u32)((l_row * GST + f4 * 4) * 4);
            cpa16(sXa + s * SSZ + off, xsrc + s * 16 + f4 * 4);
            cpa16(sWa + s * SSZ + off, wsrc + s * 16 + f4 * 4);
        }
        CP_COMMIT();
    }

    const int NC = KK / 16;   // 64 chunks
#pragma unroll 3
    for (int c = 0; c < NC; c++) {
        if (c + 2 < NC) { CP_WAIT1(); } else { CP_WAIT0(); }
        __syncthreads();

        if (c + 2 < NC) {
            const int sn = (c + 2) % 3;
#pragma unroll
            for (int i = 0; i < 2; i++) {
                int f4 = l_f4 + i * 2;
                u32 off = (u32)((l_row * GST + f4 * 4) * 4);
                cpa16(sXa + sn * SSZ + off, xsrc + (c + 2) * 16 + f4 * 4);
                cpa16(sWa + sn * SSZ + off, wsrc + (c + 2) * 16 + f4 * 4);
            }
            CP_COMMIT();
        }

        const int st = c % 3;
        const u32 bufX = sXa + (u32)(st * SSZ);
        const u32 bufW = sWa + (u32)(st * SSZ);

#pragma unroll
        for (int ks = 0; ks < 2; ks++) {
            const int kk = ks * 8;
            u32 af[4][4];
            u32 bf[4][2];
#pragma unroll
            for (int mt = 0; mt < 4; mt++) {
                u32 addr = bufX + (u32)(((wm + mt * 16 + a_row) * GST + kk + a_col) * 4);
                ldsm_x4(af[mt][0], af[mt][1], af[mt][2], af[mt][3], addr);
            }
#pragma unroll
            for (int np = 0; np < 2; np++) {
                u32 addr = bufW + (u32)(((wn + (np * 2 + b_nt) * 8 + lrw) * GST + kk + b_col) * 4);
                ldsm_x4(bf[np * 2][0], bf[np * 2][1], bf[np * 2 + 1][0], bf[np * 2 + 1][1], addr);
            }
#pragma unroll
            for (int mt = 0; mt < 4; mt++)
#pragma unroll
                for (int nt = 0; nt < 4; nt++)
                    mma_tf32(d[mt][nt][0], d[mt][nt][1], d[mt][nt][2], d[mt][nt][3],
                             af[mt][0], af[mt][1], af[mt][2], af[mt][3],
                             bf[nt][0], bf[nt][1]);
        }
    }

    // Epilogue: bias add, round to tf32 value, store.
#pragma unroll
    for (int mt = 0; mt < 4; mt++) {
        const int r0 = bm + wm + mt * 16 + lr;
#pragma unroll
        for (int nt = 0; nt < 4; nt++) {
            const int cl = wn + nt * 8 + lc * 2;
            float2 v0, v1;
            v0.x = __uint_as_float(f2tf32(d[mt][nt][0] + sBias[cl]));
            v0.y = __uint_as_float(f2tf32(d[mt][nt][1] + sBias[cl + 1]));
            v1.x = __uint_as_float(f2tf32(d[mt][nt][2] + sBias[cl]));
            v1.y = __uint_as_float(f2tf32(d[mt][nt][3] + sBias[cl + 1]));
            *(float2*)(C + (size_t)r0 * N3 + bn + cl) = v0;
            *(float2*)(C + (size_t)(r0 + 8) * N3 + bn + cl) = v1;
        }
    }
}

// ---------------------------------------------------------------------------
// Kernel 2: flash attention, mma.sync tf32, kv-tile 32, cp.async staging,
// 128 threads, q-tile 128 (2 m-tiles/warp). P relayout via per-warp smem
// round-trip (STS.64 + ldmatrix) instead of shuffles. V via scalar LDS.
// ---------------------------------------------------------------------------
#define KSTR 68
#define VSTR 72
#define PSTR 36
#define KV 32

__global__ __launch_bounds__(128) void attn_mma(
    const float* __restrict__ qkv,   // [MM, N3] tf32-valued
    float* __restrict__ out)         // [MM, DD]
{
    __shared__ u32 pool[2 * KV * KSTR + 2 * KV * VSTR];   // 35840 B
    __shared__ u32 sP[128 * PSTR];                        // 18432 B
    u32* sV = pool + 2 * KV * KSTR;
    const u32 sKa = smem_u32(pool);
    const u32 sVa = smem_u32(sV);
    const u32 sPa = smem_u32(sP);

    const int qtile = blockIdx.x;   // 0..15
    const int h     = blockIdx.y;
    const int b     = blockIdx.z;
    const int tid   = threadIdx.x;  // 0..127
    const int wid   = tid >> 5;     // 0..3
    const int lane  = tid & 31;
    const int lr    = lane >> 2;
    const int lc    = lane & 3;
    const int lm    = lane >> 3;
    const int lrw   = lane & 7;

    const float qs = 0.18033688011110793f;  // 0.125 * log2(e)

    const int l_row = tid >> 2;          // 0..31 (kv row)
    const int l_f4b = tid & 3;           // 0..3; f4 = l_f4b + 4i

    // ---- Q fragments resident: 2 m-tiles of 16 rows each ----
    u32 qa[2][8][4];
#pragma unroll
    for (int mt = 0; mt < 2; mt++) {
        const int row0 = qtile * 128 + wid * 32 + mt * 16;
        const float* q0 = qkv + ((size_t)(b * LL + row0 + lr)) * N3 + h * HD;
        const float* q1 = q0 + 8 * (size_t)N3;
#pragma unroll
        for (int kst = 0; kst < 8; kst++) {
            int kk = kst * 8;
            qa[mt][kst][0] = f2tf32(q0[kk + lc    ] * qs);
            qa[mt][kst][1] = f2tf32(q1[kk + lc    ] * qs);
            qa[mt][kst][2] = f2tf32(q0[kk + lc + 4] * qs);
            qa[mt][kst][3] = f2tf32(q1[kk + lc + 4] * qs);
        }
    }

    float o[2][8][4];
#pragma unroll
    for (int mt = 0; mt < 2; mt++)
#pragma unroll
        for (int dt = 0; dt < 8; dt++)
#pragma unroll
            for (int r = 0; r < 4; r++) o[mt][dt][r] = 0.f;
    float m_a[2] = {-1e30f, -1e30f}, m_b[2] = {-1e30f, -1e30f};
    float l_a[2] = {0.f, 0.f},       l_b[2] = {0.f, 0.f};

    const float* kvbase = qkv + (size_t)b * LL * N3 + DD + h * HD;
    const float* srcrow = kvbase + (size_t)l_row * N3;

    // prologue: tile 0 via cp.async into buffer 0
#pragma unroll
    for (int i = 0; i < 4; i++) {
        int f4 = l_f4b + i * 4;
        cpa16(sKa + (u32)((l_row * KSTR + f4 * 4) * 4), srcrow + f4 * 4);
        cpa16(sVa + (u32)((l_row * VSTR + f4 * 4) * 4), srcrow + DD + f4 * 4);
    }
    CP_COMMIT();

    const int NT = LL / KV;   // 64
    for (int kt = 0; kt < NT; kt++) {
        CP_WAIT0();
        __syncthreads();

        if (kt + 1 < NT) {
            const u32 kofs = (u32)(((kt + 1) & 1) * KV * KSTR * 4);
            const u32 vofs = (u32)(((kt + 1) & 1) * KV * VSTR * 4);
            const float* sr = srcrow + (size_t)((kt + 1) * KV) * N3;
#pragma unroll
            for (int i = 0; i < 4; i++) {
                int f4 = l_f4b + i * 4;
                cpa16(sKa + kofs + (u32)((l_row * KSTR + f4 * 4) * 4), sr + f4 * 4);
                cpa16(sVa + vofs + (u32)((l_row * VSTR + f4 * 4) * 4), sr + DD + f4 * 4);
            }
            CP_COMMIT();
        }

        const u32 bufK = sKa + (u32)((kt & 1) * KV * KSTR * 4);
        u32* bufV = sV + (kt & 1) * KV * VSTR;

        // ---- S = Q K^T : K frags shared across both m-tiles ----
        float s[2][4][4];
#pragma unroll
        for (int mt = 0; mt < 2; mt++)
#pragma unroll
            for (int nt = 0; nt < 4; nt++)
#pragma unroll
                for (int r = 0; r < 4; r++) s[mt][nt][r] = 0.f;

#pragma unroll
        for (int kst = 0; kst < 8; kst++) {
            const int kk = kst * 8;
            u32 bf[4][2];
#pragma unroll
            for (int np = 0; np < 2; np++) {
                int nt0 = np * 2 + (lm >> 1);
                u32 addr = bufK + (u32)(((nt0 * 8 + lrw) * KSTR + kk + (lm & 1) * 4) * 4);
                ldsm_x4(bf[np * 2][0], bf[np * 2][1], bf[np * 2 + 1][0], bf[np * 2 + 1][1], addr);
            }
#pragma unroll
            for (int mt = 0; mt < 2; mt++)
#pragma unroll
                for (int nt = 0; nt < 4; nt++)
                    mma_tf32(s[mt][nt][0], s[mt][nt][1], s[mt][nt][2], s[mt][nt][3],
                             qa[mt][kst][0], qa[mt][kst][1], qa[mt][kst][2], qa[mt][kst][3],
                             bf[nt][0], bf[nt][1]);
        }

        // ---- online softmax per m-tile; P written to per-warp smem ----
#pragma unroll
        for (int mt = 0; mt < 2; mt++) {
            float mx_a = -1e30f, mx_b = -1e30f;
#pragma unroll
            for (int nt = 0; nt < 4; nt++) {
                mx_a = fmaxf(mx_a, fmaxf(s[mt][nt][0], s[mt][nt][1]));
                mx_b = fmaxf(mx_b, fmaxf(s[mt][nt][2], s[mt][nt][3]));
            }
            mx_a = fmaxf(mx_a, __shfl_xor_sync(0xffffffffu, mx_a, 1));
            mx_a = fmaxf(mx_a, __shfl_xor_sync(0xffffffffu, mx_a, 2));
            mx_b = fmaxf(mx_b, __shfl_xor_sync(0xffffffffu, mx_b, 1));
            mx_b = fmaxf(mx_b, __shfl_xor_sync(0xffffffffu, mx_b, 2));

            float nm_a = fmaxf(m_a[mt], mx_a);
            float nm_b = fmaxf(m_b[mt], mx_b);
            float ca = ex2(m_a[mt] - nm_a);
            float cb = ex2(m_b[mt] - nm_b);
            m_a[mt] = nm_a; m_b[mt] = nm_b;
            l_a[mt] *= ca;  l_b[mt] *= cb;
#pragma unroll
            for (int dt = 0; dt < 8; dt++) {
                o[mt][dt][0] *= ca; o[mt][dt][1] *= ca;
                o[mt][dt][2] *= cb; o[mt][dt][3] *= cb;
            }
            const int ra = wid * 32 + mt * 16 + lr;
#pragma unroll
            for (int nt = 0; nt < 4; nt++) {
                float p0 = ex2(s[mt][nt][0] - m_a[mt]);
                float p1 = ex2(s[mt][nt][1] - m_a[mt]);
                float p2 = ex2(s[mt][nt][2] - m_b[mt]);
                float p3 = ex2(s[mt][nt][3] - m_b[mt]);
                l_a[mt] += p0 + p1;
                l_b[mt] += p2 + p3;
                *(uint2*)&sP[ra * PSTR + nt * 8 + lc * 2] =
                    make_uint2(f2tf32(p0), f2tf32(p1));
                *(uint2*)&sP[(ra + 8) * PSTR + nt * 8 + lc * 2] =
                    make_uint2(f2tf32(p2), f2tf32(p3));
            }
        }
        __syncwarp();

        // ---- O += P V : P A-frags via ldmatrix, V via scalar LDS ----
#pragma unroll
        for (int jt = 0; jt < 4; jt++) {
            u32 A[2][4];
#pragma unroll
            for (int mt = 0; mt < 2; mt++) {
                u32 addr = sPa + (u32)(((wid * 32 + mt * 16 + (lm & 1) * 8 + lrw) * PSTR
                                        + jt * 8 + (lm >> 1) * 4) * 4);
                ldsm_x4(A[mt][0], A[mt][1], A[mt][2], A[mt][3], addr);
            }
#pragma unroll
            for (int dt = 0; dt < 8; dt++) {
                u32 b0 = bufV[(jt * 8 + lc    ) * VSTR + dt * 8 + lr];
                u32 b1 = bufV[(jt * 8 + lc + 4) * VSTR + dt * 8 + lr];
                mma_tf32(o[0][dt][0], o[0][dt][1], o[0][dt][2], o[0][dt][3],
                         A[0][0], A[0][1], A[0][2], A[0][3], b0, b1);
                mma_tf32(o[1][dt][0], o[1][dt][1], o[1][dt][2], o[1][dt][3],
                         A[1][0], A[1][1], A[1][2], A[1][3], b0, b1);
            }
        }
        __syncthreads();   // all warps done with buf kt before cpa overwrites it
    }

    // ---- final reduce + normalize ----
    float inv_a[2], inv_b[2];
#pragma unroll
    for (int mt = 0; mt < 2; mt++) {
        l_a[mt] += __shfl_xor_sync(0xffffffffu, l_a[mt], 1);
        l_a[mt] += __shfl_xor_sync(0xffffffffu, l_a[mt], 2);
        l_b[mt] += __shfl_xor_sync(0xffffffffu, l_b[mt], 1);
        l_b[mt] += __shfl_xor_sync(0xffffffffu, l_b[mt], 2);
        inv_a[mt] = 1.f / l_a[mt];
        inv_b[mt] = 1.f / l_b[mt];
    }

    // ---- stage O (128 rows, stride 68 = 34816 B <= pool) then store ----
    float* stage = (float*)pool;
    {
#pragma unroll
        for (int mt = 0; mt < 2; mt++) {
            const int ra = wid * 32 + mt * 16 + lr;
            const int rb = ra + 8;
#pragma unroll
            for (int dt = 0; dt < 8; dt++) {
                float2 va, vb;
                va.x = o[mt][dt][0] * inv_a[mt]; va.y = o[mt][dt][1] * inv_a[mt];
                vb.x = o[mt][dt][2] * inv_b[mt]; vb.y = o[mt][dt][3] * inv_b[mt];
                *(float2*)&stage[ra * 68 + dt * 8 + lc * 2] = va;
                *(float2*)&stage[rb * 68 + dt * 8 + lc * 2] = vb;
            }
        }
    }
    __syncthreads();
    {
        const int cr = tid >> 4;     // 0..7
        const int cc = tid & 15;     // 0..15
#pragma unroll
        for (int pass = 0; pass < 16; pass++) {
            int row = pass * 8 + cr;
            float4 v = *(const float4*)&stage[row * 68 + cc * 4];
            *(float4*)(out + ((size_t)(b * LL + qtile * 128 + row)) * DD + h * HD + cc * 4) = v;
        }
    }
}

// ---------------------------------------------------------------------------
extern "C" void kernel_launch(void* const* d_in, const int* in_sizes, int n_in,
                              void* d_out, int out_size)
{
    const float* x    = (const float*)d_in[0];
    const float* W    = (const float*)d_in[1];
    const float* bias = (const float*)d_in[2];
    float* out = (float*)d_out;

    float *qkv, *xc, *wc;
    cudaGetSymbolAddress((void**)&qkv, g_qkv);
    cudaGetSymbolAddress((void**)&xc,  g_xc);
    cudaGetSymbolAddress((void**)&wc,  g_wc);

    const size_t nf4 = ((size_t)MM * KK + (size_t)N3 * KK) / 4;
    cvt_prepass<<<(unsigned)((nf4 + 255) / 256), 256>>>(x, W, xc, wc);

    dim3 ggrid(N3 / 128, MM / 128);  // (24, 32)
    qkv_gemm_mma<<<ggrid, 256>>>(xc, wc, bias, qkv);

    dim3 agrid(LL / 128, NH, BB);    // (16, 16, 2)
    attn_mma<<<agrid, 128>>>(qkv, out);
}

// round 16
// speedup vs baseline: 1.0318x; 1.0318x over previous
#include <cuda_runtime.h>
#include <cuda_bf16.h>
#include <cstdint>

// Problem constants
#define BB 2
#define LL 2048
#define DD 1024
#define NH 16
#define HD 64
#define MM (BB*LL)      // 4096
#define N3 (3*DD)       // 3072
#define KK DD           // 1024

typedef unsigned long long u64;
typedef unsigned int u32;

// ---- tf32 mma.sync helpers ----
__device__ __forceinline__ u32 f2tf32(float f) {
    u32 r; asm("cvt.rna.tf32.f32 %0, %1;" : "=r"(r) : "f"(f)); return r;
}
__device__ __forceinline__ void mma_tf32(float& d0, float& d1, float& d2, float& d3,
                                         u32 a0, u32 a1, u32 a2, u32 a3,
                                         u32 b0, u32 b1) {
    asm volatile(
        "mma.sync.aligned.m16n8k8.row.col.f32.tf32.tf32.f32 "
        "{%0,%1,%2,%3}, {%4,%5,%6,%7}, {%8,%9}, {%0,%1,%2,%3};"
        : "+f"(d0), "+f"(d1), "+f"(d2), "+f"(d3)
        : "r"(a0), "r"(a1), "r"(a2), "r"(a3), "r"(b0), "r"(b1));
}
__device__ __forceinline__ float ex2(float x) {
    float y; asm("ex2.approx.f32 %0, %1;" : "=f"(y) : "f"(x)); return y;
}
__device__ __forceinline__ u32 smem_u32(const void* p) {
    u32 a;
    asm("{ .reg .u64 t; cvta.to.shared.u64 t, %1; cvt.u32.u64 %0, t; }" : "=r"(a) : "l"(p));
    return a;
}
__device__ __forceinline__ void ldsm_x4(u32& r0, u32& r1, u32& r2, u32& r3, u32 addr) {
    asm volatile("ldmatrix.sync.aligned.m8n8.x4.shared.b16 {%0,%1,%2,%3}, [%4];"
                 : "=r"(r0), "=r"(r1), "=r"(r2), "=r"(r3) : "r"(addr));
}
__device__ __forceinline__ void cpa16(u32 dst, const void* src) {
    asm volatile("cp.async.cg.shared.global [%0], [%1], 16;" :: "r"(dst), "l"(src) : "memory");
}
#define CP_COMMIT() asm volatile("cp.async.commit_group;" ::: "memory")
#define CP_WAIT0()  asm volatile("cp.async.wait_group 0;" ::: "memory")
#define CP_WAIT1()  asm volatile("cp.async.wait_group 1;" ::: "memory")

// Scratch: qkv [4096,3072] f32 (tf32-rounded values); pre-rounded x and W.
__device__ float g_qkv[(size_t)MM * N3];
__device__ float g_xc[(size_t)MM * KK];
__device__ float g_wc[(size_t)N3 * KK];

// ---------------------------------------------------------------------------
// Kernel 0: pre-pass — rna-round x and W to tf32 values (stored as f32 bits).
// ---------------------------------------------------------------------------
__global__ void cvt_prepass(const float* __restrict__ x, const float* __restrict__ W,
                            float* __restrict__ xc, float* __restrict__ wc)
{
    const size_t nx4 = (size_t)MM * KK / 4;
    const size_t nw4 = (size_t)N3 * KK / 4;
    size_t i = (size_t)blockIdx.x * blockDim.x + threadIdx.x;
    if (i < nx4) {
        float4 v = ((const float4*)x)[i];
        ((uint4*)xc)[i] = make_uint4(f2tf32(v.x), f2tf32(v.y), f2tf32(v.z), f2tf32(v.w));
    } else if (i < nx4 + nw4) {
        size_t j = i - nx4;
        float4 v = ((const float4*)W)[j];
        ((uint4*)wc)[j] = make_uint4(f2tf32(v.x), f2tf32(v.y), f2tf32(v.z), f2tf32(v.w));
    }
}

// ---------------------------------------------------------------------------
// Kernel 1: QKV GEMM, mma.sync tf32, 2-STAGE cp.async pipeline, K-chunk 16.
// smem row stride 20 floats (80 B: aligned + LDSM conflict-free).
// smem = 2 x 2 x 10.24 KB = 41 KB static -> 2 CTAs/SM.
// ---------------------------------------------------------------------------
#define GST 20

__global__ __launch_bounds__(256, 2) void qkv_gemm_mma(
    const float* __restrict__ x,     // pre-rounded [MM, KK]
    const float* __restrict__ W,     // pre-rounded [N3, KK]
    const float* __restrict__ bias,
    float* __restrict__ C)           // [MM, N3] (tf32-rounded values)
{
    __shared__ u32 sX[2 * 128 * GST];   // 20480 B
    __shared__ u32 sW[2 * 128 * GST];   // 20480 B
    __shared__ float sBias[128];

    const int bm = blockIdx.y * 128;
    const int bn = blockIdx.x * 128;
    const int tid  = threadIdx.x;
    const int wid  = tid >> 5;
    const int lane = tid & 31;
    const int wm = (wid >> 2) * 64;
    const int wn = (wid & 3) * 32;
    const int lr = lane >> 2;
    const int lc = lane & 3;

    // chunk load: 128 rows x 16 k = 512 f4 per matrix; 2 per thread each
    const int l_row = tid >> 1;      // 0..127
    const int l_f4  = tid & 1;       // f4 = l_f4 + 2i, i in {0,1}

    const u32 sXa = smem_u32(sX);
    const u32 sWa = smem_u32(sW);
    const u32 SSZ = 128 * GST * 4;   // bytes per stage
    const float* xsrc = x + (size_t)(bm + l_row) * KK;
    const float* wsrc = W + (size_t)(bn + l_row) * KK;

    const int lm  = lane >> 3;
    const int lrw = lane & 7;
    const int a_row = (lm & 1) * 8 + lrw;
    const int a_col = (lm >> 1) * 4;
    const int b_nt  = lm >> 1;
    const int b_col = (lm & 1) * 4;

    float d[4][4][4];
#pragma unroll
    for (int mt = 0; mt < 4; mt++)
#pragma unroll
        for (int nt = 0; nt < 4; nt++)
#pragma unroll
            for (int r = 0; r < 4; r++) d[mt][nt][r] = 0.f;

    if (tid < 128) sBias[tid] = bias[bn + tid];

    // prologue: stage 0 in flight
#pragma unroll
    for (int i = 0; i < 2; i++) {
        int f4 = l_f4 + i * 2;
        u32 off = (u32)((l_row * GST + f4 * 4) * 4);
        cpa16(sXa + off, xsrc + f4 * 4);
        cpa16(sWa + off, wsrc + f4 * 4);
    }
    CP_COMMIT();

    const int NC = KK / 16;   // 64 chunks
#pragma unroll 2
    for (int c = 0; c < NC; c++) {
        CP_WAIT0();
        __syncthreads();

        // prefetch chunk c+1 into the other stage (1 compute phase lookahead)
        if (c + 1 < NC) {
            const u32 sn = (u32)(((c + 1) & 1) * SSZ);
#pragma unroll
            for (int i = 0; i < 2; i++) {
                int f4 = l_f4 + i * 2;
                u32 off = (u32)((l_row * GST + f4 * 4) * 4);
                cpa16(sXa + sn + off, xsrc + (c + 1) * 16 + f4 * 4);
                cpa16(sWa + sn + off, wsrc + (c + 1) * 16 + f4 * 4);
            }
            CP_COMMIT();
        }

        const u32 bufX = sXa + (u32)((c & 1) * SSZ);
        const u32 bufW = sWa + (u32)((c & 1) * SSZ);

#pragma unroll
        for (int ks = 0; ks < 2; ks++) {
            const int kk = ks * 8;
            u32 af[4][4];
            u32 bf[4][2];
#pragma unroll
            for (int mt = 0; mt < 4; mt++) {
                u32 addr = bufX + (u32)(((wm + mt * 16 + a_row) * GST + kk + a_col) * 4);
                ldsm_x4(af[mt][0], af[mt][1], af[mt][2], af[mt][3], addr);
            }
#pragma unroll
            for (int np = 0; np < 2; np++) {
                u32 addr = bufW + (u32)(((wn + (np * 2 + b_nt) * 8 + lrw) * GST + kk + b_col) * 4);
                ldsm_x4(bf[np * 2][0], bf[np * 2][1], bf[np * 2 + 1][0], bf[np * 2 + 1][1], addr);
            }
#pragma unroll
            for (int mt = 0; mt < 4; mt++)
#pragma unroll
                for (int nt = 0; nt < 4; nt++)
                    mma_tf32(d[mt][nt][0], d[mt][nt][1], d[mt][nt][2], d[mt][nt][3],
                             af[mt][0], af[mt][1], af[mt][2], af[mt][3],
                             bf[nt][0], bf[nt][1]);
        }
        __syncthreads();   // everyone done reading stage c before its reuse at c+2
    }

    // Epilogue: bias add, round to tf32 value, store.
#pragma unroll
    for (int mt = 0; mt < 4; mt++) {
        const int r0 = bm + wm + mt * 16 + lr;
#pragma unroll
        for (int nt = 0; nt < 4; nt++) {
            const int cl = wn + nt * 8 + lc * 2;
            float2 v0, v1;
            v0.x = __uint_as_float(f2tf32(d[mt][nt][0] + sBias[cl]));
            v0.y = __uint_as_float(f2tf32(d[mt][nt][1] + sBias[cl + 1]));
            v1.x = __uint_as_float(f2tf32(d[mt][nt][2] + sBias[cl]));
            v1.y = __uint_as_float(f2tf32(d[mt][nt][3] + sBias[cl + 1]));
            *(float2*)(C + (size_t)r0 * N3 + bn + cl) = v0;
            *(float2*)(C + (size_t)(r0 + 8) * N3 + bn + cl) = v1;
        }
    }
}

// ---------------------------------------------------------------------------
// Kernel 2: flash attention (R14): mma.sync tf32, kv-tile 32, cp.async
// staging, 128 threads, q-tile 128 (2 m-tiles/warp), shuffle-based P relayout.
// ---------------------------------------------------------------------------
#define KSTR 68
#define VSTR 72
#define KV 32

__global__ __launch_bounds__(128) void attn_mma(
    const float* __restrict__ qkv,   // [MM, N3] tf32-valued
    float* __restrict__ out)         // [MM, DD]
{
    __shared__ u32 pool[2 * KV * KSTR + 2 * KV * VSTR];   // 35840 B
    u32* sV = pool + 2 * KV * KSTR;
    const u32 sKa = smem_u32(pool);
    const u32 sVa = smem_u32(sV);

    const int qtile = blockIdx.x;   // 0..15
    const int h     = blockIdx.y;
    const int b     = blockIdx.z;
    const int tid   = threadIdx.x;  // 0..127
    const int wid   = tid >> 5;     // 0..3
    const int lane  = tid & 31;
    const int lr    = lane >> 2;
    const int lc    = lane & 3;
    const int lm    = lane >> 3;
    const int lrw   = lane & 7;

    const float qs = 0.18033688011110793f;  // 0.125 * log2(e)

    const int l_row = tid >> 2;          // 0..31 (kv row)
    const int l_f4b = tid & 3;           // 0..3; f4 = l_f4b + 4i

    // ---- Q fragments resident: 2 m-tiles of 16 rows each ----
    u32 qa[2][8][4];
#pragma unroll
    for (int mt = 0; mt < 2; mt++) {
        const int row0 = qtile * 128 + wid * 32 + mt * 16;
        const float* q0 = qkv + ((size_t)(b * LL + row0 + lr)) * N3 + h * HD;
        const float* q1 = q0 + 8 * (size_t)N3;
#pragma unroll
        for (int kst = 0; kst < 8; kst++) {
            int kk = kst * 8;
            qa[mt][kst][0] = f2tf32(q0[kk + lc    ] * qs);
            qa[mt][kst][1] = f2tf32(q1[kk + lc    ] * qs);
            qa[mt][kst][2] = f2tf32(q0[kk + lc + 4] * qs);
            qa[mt][kst][3] = f2tf32(q1[kk + lc + 4] * qs);
        }
    }

    float o[2][8][4];
#pragma unroll
    for (int mt = 0; mt < 2; mt++)
#pragma unroll
        for (int dt = 0; dt < 8; dt++)
#pragma unroll
            for (int r = 0; r < 4; r++) o[mt][dt][r] = 0.f;
    float m_a[2] = {-1e30f, -1e30f}, m_b[2] = {-1e30f, -1e30f};
    float l_a[2] = {0.f, 0.f},       l_b[2] = {0.f, 0.f};

    const float* kvbase = qkv + (size_t)b * LL * N3 + DD + h * HD;
    const float* srcrow = kvbase + (size_t)l_row * N3;

    // prologue: tile 0 via cp.async into buffer 0
#pragma unroll
    for (int i = 0; i < 4; i++) {
        int f4 = l_f4b + i * 4;
        cpa16(sKa + (u32)((l_row * KSTR + f4 * 4) * 4), srcrow + f4 * 4);
        cpa16(sVa + (u32)((l_row * VSTR + f4 * 4) * 4), srcrow + DD + f4 * 4);
    }
    CP_COMMIT();

    const int NT = LL / KV;   // 64
    for (int kt = 0; kt < NT; kt++) {
        CP_WAIT0();
        __syncthreads();

        if (kt + 1 < NT) {
            const u32 kofs = (u32)(((kt + 1) & 1) * KV * KSTR * 4);
            const u32 vofs = (u32)(((kt + 1) & 1) * KV * VSTR * 4);
            const float* sr = srcrow + (size_t)((kt + 1) * KV) * N3;
#pragma unroll
            for (int i = 0; i < 4; i++) {
                int f4 = l_f4b + i * 4;
                cpa16(sKa + kofs + (u32)((l_row * KSTR + f4 * 4) * 4), sr + f4 * 4);
                cpa16(sVa + vofs + (u32)((l_row * VSTR + f4 * 4) * 4), sr + DD + f4 * 4);
            }
            CP_COMMIT();
        }

        const u32 bufK = sKa + (u32)((kt & 1) * KV * KSTR * 4);
        u32* bufV = sV + (kt & 1) * KV * VSTR;

        // ---- S = Q K^T : K frags shared across both m-tiles ----
        float s[2][4][4];
#pragma unroll
        for (int mt = 0; mt < 2; mt++)
#pragma unroll
            for (int nt = 0; nt < 4; nt++)
#pragma unroll
                for (int r = 0; r < 4; r++) s[mt][nt][r] = 0.f;

#pragma unroll
        for (int kst = 0; kst < 8; kst++) {
            const int kk = kst * 8;
            u32 bf[4][2];
#pragma unroll
            for (int np = 0; np < 2; np++) {
                int nt0 = np * 2 + (lm >> 1);
                u32 addr = bufK + (u32)(((nt0 * 8 + lrw) * KSTR + kk + (lm & 1) * 4) * 4);
                ldsm_x4(bf[np * 2][0], bf[np * 2][1], bf[np * 2 + 1][0], bf[np * 2 + 1][1], addr);
            }
#pragma unroll
            for (int mt = 0; mt < 2; mt++)
#pragma unroll
                for (int nt = 0; nt < 4; nt++)
                    mma_tf32(s[mt][nt][0], s[mt][nt][1], s[mt][nt][2], s[mt][nt][3],
                             qa[mt][kst][0], qa[mt][kst][1], qa[mt][kst][2], qa[mt][kst][3],
                             bf[nt][0], bf[nt][1]);
        }

        // ---- online softmax per m-tile; p in A-operand u32 form ----
        u32 p[2][4][4];
#pragma unroll
        for (int mt = 0; mt < 2; mt++) {
            float mx_a = -1e30f, mx_b = -1e30f;
#pragma unroll
            for (int nt = 0; nt < 4; nt++) {
                mx_a = fmaxf(mx_a, fmaxf(s[mt][nt][0], s[mt][nt][1]));
                mx_b = fmaxf(mx_b, fmaxf(s[mt][nt][2], s[mt][nt][3]));
            }
            mx_a = fmaxf(mx_a, __shfl_xor_sync(0xffffffffu, mx_a, 1));
            mx_a = fmaxf(mx_a, __shfl_xor_sync(0xffffffffu, mx_a, 2));
            mx_b = fmaxf(mx_b, __shfl_xor_sync(0xffffffffu, mx_b, 1));
            mx_b = fmaxf(mx_b, __shfl_xor_sync(0xffffffffu, mx_b, 2));

            float nm_a = fmaxf(m_a[mt], mx_a);
            float nm_b = fmaxf(m_b[mt], mx_b);
            float ca = ex2(m_a[mt] - nm_a);
            float cb = ex2(m_b[mt] - nm_b);
            m_a[mt] = nm_a; m_b[mt] = nm_b;
            l_a[mt] *= ca;  l_b[mt] *= cb;
#pragma unroll
            for (int dt = 0; dt < 8; dt++) {
                o[mt][dt][0] *= ca; o[mt][dt][1] *= ca;
                o[mt][dt][2] *= cb; o[mt][dt][3] *= cb;
            }
#pragma unroll
            for (int nt = 0; nt < 4; nt++) {
                float p0 = ex2(s[mt][nt][0] - m_a[mt]);
                float p1 = ex2(s[mt][nt][1] - m_a[mt]);
                float p2 = ex2(s[mt][nt][2] - m_b[mt]);
                float p3 = ex2(s[mt][nt][3] - m_b[mt]);
                l_a[mt] += p0 + p1;
                l_b[mt] += p2 + p3;
                p[mt][nt][0] = f2tf32(p0); p[mt][nt][1] = f2tf32(p1);
                p[mt][nt][2] = f2tf32(p2); p[mt][nt][3] = f2tf32(p3);
            }
        }

        // ---- O += P V : V frags shared across both m-tiles ----
        const int s0 = lr * 4 + (lc >> 1);
        const int s2 = s0 + 2;
        const bool odd = (lc & 1);
#pragma unroll
        for (int jt = 0; jt < 4; jt++) {
            u32 A[2][4];
#pragma unroll
            for (int mt = 0; mt < 2; mt++) {
                u32 v00 = __shfl_sync(0xffffffffu, p[mt][jt][0], s0);
                u32 v01 = __shfl_sync(0xffffffffu, p[mt][jt][1], s0);
                u32 v20 = __shfl_sync(0xffffffffu, p[mt][jt][0], s2);
                u32 v21 = __shfl_sync(0xffffffffu, p[mt][jt][1], s2);
                u32 w00 = __shfl_sync(0xffffffffu, p[mt][jt][2], s0);
                u32 w01 = __shfl_sync(0xffffffffu, p[mt][jt][3], s0);
                u32 w20 = __shfl_sync(0xffffffffu, p[mt][jt][2], s2);
                u32 w21 = __shfl_sync(0xffffffffu, p[mt][jt][3], s2);
                A[mt][0] = odd ? v01 : v00;
                A[mt][2] = odd ? v21 : v20;
                A[mt][1] = odd ? w01 : w00;
                A[mt][3] = odd ? w21 : w20;
            }
#pragma unroll
            for (int dt = 0; dt < 8; dt++) {
                u32 b0 = bufV[(jt * 8 + lc    ) * VSTR + dt * 8 + lr];
                u32 b1 = bufV[(jt * 8 + lc + 4) * VSTR + dt * 8 + lr];
                mma_tf32(o[0][dt][0], o[0][dt][1], o[0][dt][2], o[0][dt][3],
                         A[0][0], A[0][1], A[0][2], A[0][3], b0, b1);
                mma_tf32(o[1][dt][0], o[1][dt][1], o[1][dt][2], o[1][dt][3],
                         A[1][0], A[1][1], A[1][2], A[1][3], b0, b1);
            }
        }
        __syncthreads();   // all warps done with buf kt before cpa overwrites it
    }

    // ---- final reduce + normalize ----
    float inv_a[2], inv_b[2];
#pragma unroll
    for (int mt = 0; mt < 2; mt++) {
        l_a[mt] += __shfl_xor_sync(0xffffffffu, l_a[mt], 1);
        l_a[mt] += __shfl_xor_sync(0xffffffffu, l_a[mt], 2);
        l_b[mt] += __shfl_xor_sync(0xffffffffu, l_b[mt], 1);
        l_b[mt] += __shfl_xor_sync(0xffffffffu, l_b[mt], 2);
        inv_a[mt] = 1.f / l_a[mt];
        inv_b[mt] = 1.f / l_b[mt];
    }

    // ---- stage O (128 rows, stride 68 = 34816 B <= pool) then store ----
    float* stage = (float*)pool;
    {
#pragma unroll
        for (int mt = 0; mt < 2; mt++) {
            const int ra = wid * 32 + mt * 16 + lr;
            const int rb = ra + 8;
#pragma unroll
            for (int dt = 0; dt < 8; dt++) {
                float2 va, vb;
                va.x = o[mt][dt][0] * inv_a[mt]; va.y = o[mt][dt][1] * inv_a[mt];
                vb.x = o[mt][dt][2] * inv_b[mt]; vb.y = o[mt][dt][3] * inv_b[mt];
                *(float2*)&stage[ra * 68 + dt * 8 + lc * 2] = va;
                *(float2*)&stage[rb * 68 + dt * 8 + lc * 2] = vb;
            }
        }
    }
    __syncthreads();
    {
        const int cr = tid >> 4;     // 0..7
        const int cc = tid & 15;     // 0..15
#pragma unroll
        for (int pass = 0; pass < 16; pass++) {
            int row = pass * 8 + cr;
            float4 v = *(const float4*)&stage[row * 68 + cc * 4];
            *(float4*)(out + ((size_t)(b * LL + qtile * 128 + row)) * DD + h * HD + cc * 4) = v;
        }
    }
}

// ---------------------------------------------------------------------------
extern "C" void kernel_launch(void* const* d_in, const int* in_sizes, int n_in,
                              void* d_out, int out_size)
{
    const float* x    = (const float*)d_in[0];
    const float* W    = (const float*)d_in[1];
    const float* bias = (const float*)d_in[2];
    float* out = (float*)d_out;

    float *qkv, *xc, *wc;
    cudaGetSymbolAddress((void**)&qkv, g_qkv);
    cudaGetSymbolAddress((void**)&xc,  g_xc);
    cudaGetSymbolAddress((void**)&wc,  g_wc);

    const size_t nf4 = ((size_t)MM * KK + (size_t)N3 * KK) / 4;
    cvt_prepass<<<(unsigned)((nf4 + 255) / 256), 256>>>(x, W, xc, wc);

    dim3 ggrid(N3 / 128, MM / 128);  // (24, 32)
    qkv_gemm_mma<<<ggrid, 256>>>(xc, wc, bias, qkv);

    dim3 agrid(LL / 128, NH, BB);    // (16, 16, 2)
    attn_mma<<<agrid, 128>>>(qkv, out);
}

// round 17
// speedup vs baseline: 1.9888x; 1.9274x over previous
#include <cuda_runtime.h>
#include <cuda_fp16.h>
#include <cstdint>

// Problem constants
#define BB 2
#define LL 2048
#define DD 1024
#define NH 16
#define HD 64
#define MM (BB*LL)      // 4096
#define N3 (3*DD)       // 3072
#define KK DD           // 1024

typedef unsigned long long u64;
typedef unsigned int u32;

// ---- helpers ----
__device__ __forceinline__ u32 pack_h2(float lo, float hi) {
    u32 r; asm("cvt.rn.f16x2.f32 %0, %1, %2;" : "=r"(r) : "f"(hi), "f"(lo)); return r;
}
__device__ __forceinline__ void mma_f16(float& d0, float& d1, float& d2, float& d3,
                                        u32 a0, u32 a1, u32 a2, u32 a3,
                                        u32 b0, u32 b1) {
    asm volatile(
        "mma.sync.aligned.m16n8k16.row.col.f32.f16.f16.f32 "
        "{%0,%1,%2,%3}, {%4,%5,%6,%7}, {%8,%9}, {%0,%1,%2,%3};"
        : "+f"(d0), "+f"(d1), "+f"(d2), "+f"(d3)
        : "r"(a0), "r"(a1), "r"(a2), "r"(a3), "r"(b0), "r"(b1));
}
__device__ __forceinline__ float ex2(float x) {
    float y; asm("ex2.approx.f32 %0, %1;" : "=f"(y) : "f"(x)); return y;
}
__device__ __forceinline__ u32 smem_u32(const void* p) {
    u32 a;
    asm("{ .reg .u64 t; cvta.to.shared.u64 t, %1; cvt.u32.u64 %0, t; }" : "=r"(a) : "l"(p));
    return a;
}
__device__ __forceinline__ void ldsm_x4(u32& r0, u32& r1, u32& r2, u32& r3, u32 addr) {
    asm volatile("ldmatrix.sync.aligned.m8n8.x4.shared.b16 {%0,%1,%2,%3}, [%4];"
                 : "=r"(r0), "=r"(r1), "=r"(r2), "=r"(r3) : "r"(addr));
}
__device__ __forceinline__ void ldsm_x4_t(u32& r0, u32& r1, u32& r2, u32& r3, u32 addr) {
    asm volatile("ldmatrix.sync.aligned.m8n8.x4.trans.shared.b16 {%0,%1,%2,%3}, [%4];"
                 : "=r"(r0), "=r"(r1), "=r"(r2), "=r"(r3) : "r"(addr));
}
__device__ __forceinline__ void cpa16(u32 dst, const void* src) {
    asm volatile("cp.async.cg.shared.global [%0], [%1], 16;" :: "r"(dst), "l"(src) : "memory");
}
#define CP_COMMIT() asm volatile("cp.async.commit_group;" ::: "memory")
#define CP_WAIT0()  asm volatile("cp.async.wait_group 0;" ::: "memory")
#define CP_WAIT1()  asm volatile("cp.async.wait_group 1;" ::: "memory")

// Scratch: qkv fp16 (Q pre-scaled by 0.125*log2e), pre-converted fp16 x and W.
__device__ __half g_qkvh[(size_t)MM * N3];
__device__ __half g_xh[(size_t)MM * KK];
__device__ __half g_wh[(size_t)N3 * KK];

// ---------------------------------------------------------------------------
// Kernel 0: pre-pass — convert x and W to fp16 (rn). 8 f32 per thread.
// ---------------------------------------------------------------------------
__global__ void cvt_prepass(const float* __restrict__ x, const float* __restrict__ W,
                            __half* __restrict__ xh, __half* __restrict__ wh)
{
    const size_t nx8 = (size_t)MM * KK / 8;
    const size_t nw8 = (size_t)N3 * KK / 8;
    size_t i = (size_t)blockIdx.x * blockDim.x + threadIdx.x;
    const float4* src; u32* dst; size_t j;
    if (i < nx8)            { src = (const float4*)x; dst = (u32*)xh; j = i; }
    else if (i < nx8 + nw8) { src = (const float4*)W; dst = (u32*)wh; j = i - nx8; }
    else return;
    float4 a = src[j * 2];
    float4 b = src[j * 2 + 1];
    uint4 r;
    r.x = pack_h2(a.x, a.y); r.y = pack_h2(a.z, a.w);
    r.z = pack_h2(b.x, b.y); r.w = pack_h2(b.z, b.w);
    ((uint4*)dst)[j] = r;
}

// ---------------------------------------------------------------------------
// Kernel 1: QKV GEMM, mma.sync fp16 (m16n8k16), 3-stage cp.async, K-chunk 16.
// smem row stride 24 halfs (48 B: aligned + LDSM conflict-free (3r mod 8)).
// 36.9 KB smem -> 2 CTAs/SM. 256 thr = 8 warps (2m x 4n), warp tile 64x32.
// Epilogue: +bias, pre-scale Q block by 0.125*log2(e), store fp16.
// ---------------------------------------------------------------------------
#define HST 24

__global__ __launch_bounds__(256, 2) void qkv_gemm_mma(
    const __half* __restrict__ x,    // [MM, KK] fp16
    const __half* __restrict__ W,    // [N3, KK] fp16
    const float* __restrict__ bias,
    __half* __restrict__ C)          // [MM, N3] fp16
{
    __shared__ __half sX[3 * 128 * HST];   // 18432 B
    __shared__ __half sW[3 * 128 * HST];
    __shared__ float sBias[128];

    const int bm = blockIdx.y * 128;
    const int bn = blockIdx.x * 128;
    const int tid  = threadIdx.x;
    const int wid  = tid >> 5;
    const int lane = tid & 31;
    const int wm = (wid >> 2) * 64;
    const int wn = (wid & 3) * 32;
    const int lr = lane >> 2;
    const int lc = lane & 3;
    const int lm  = lane >> 3;
    const int lrw = lane & 7;

    // chunk load: 128 rows x 16 halfs = 2 segs/row; 256 per matrix; 1/thread
    const int l_row = tid >> 1;      // 0..127
    const int l_seg = tid & 1;       // 0..1

    const u32 sXa = smem_u32(sX);
    const u32 sWa = smem_u32(sW);
    const u32 SSZ = 128 * HST * 2;   // bytes per stage (6144)
    const u32 dOff = (u32)(l_row * HST * 2 + l_seg * 16);
    const __half* xsrc = x + (size_t)(bm + l_row) * KK + l_seg * 8;
    const __half* wsrc = W + (size_t)(bn + l_row) * KK + l_seg * 8;

    float d[4][4][4];
#pragma unroll
    for (int mt = 0; mt < 4; mt++)
#pragma unroll
        for (int nt = 0; nt < 4; nt++)
#pragma unroll
            for (int r = 0; r < 4; r++) d[mt][nt][r] = 0.f;

    if (tid < 128) sBias[tid] = bias[bn + tid];

    // prologue: stages 0,1 in flight
#pragma unroll
    for (int s = 0; s < 2; s++) {
        cpa16(sXa + s * SSZ + dOff, xsrc + s * 16);
        cpa16(sWa + s * SSZ + dOff, wsrc + s * 16);
        CP_COMMIT();
    }

    const int NC = KK / 16;   // 64 chunks
#pragma unroll 3
    for (int c = 0; c < NC; c++) {
        if (c + 2 < NC) { CP_WAIT1(); } else { CP_WAIT0(); }
        __syncthreads();

        if (c + 2 < NC) {
            const int sn = (c + 2) % 3;
            cpa16(sXa + sn * SSZ + dOff, xsrc + (c + 2) * 16);
            cpa16(sWa + sn * SSZ + dOff, wsrc + (c + 2) * 16);
            CP_COMMIT();
        }

        const int st = c % 3;
        const u32 bufX = sXa + (u32)(st * SSZ);
        const u32 bufW = sWa + (u32)(st * SSZ);

        u32 af[4][4];
        u32 bf[4][2];
        // A: m0=(rows, k0-7) m1=(rows+8, k0-7) m2=(rows, k8-15) m3=(rows+8, k8-15)
#pragma unroll
        for (int mt = 0; mt < 4; mt++) {
            u32 addr = bufX + (u32)(((wm + mt * 16 + (lm & 1) * 8 + lrw) * HST
                                     + (lm >> 1) * 8) * 2);
            ldsm_x4(af[mt][0], af[mt][1], af[mt][2], af[mt][3], addr);
        }
        // B: m0=(nt rows, k0-7) m1=(nt, k8-15) m2=(nt+1, k0-7) m3=(nt+1, k8-15)
#pragma unroll
        for (int np = 0; np < 2; np++) {
            u32 addr = bufW + (u32)(((wn + np * 16 + (lm >> 1) * 8 + lrw) * HST
                                     + (lm & 1) * 8) * 2);
            ldsm_x4(bf[np * 2][0], bf[np * 2][1], bf[np * 2 + 1][0], bf[np * 2 + 1][1], addr);
        }
#pragma unroll
        for (int mt = 0; mt < 4; mt++)
#pragma unroll
            for (int nt = 0; nt < 4; nt++)
                mma_f16(d[mt][nt][0], d[mt][nt][1], d[mt][nt][2], d[mt][nt][3],
                        af[mt][0], af[mt][1], af[mt][2], af[mt][3],
                        bf[nt][0], bf[nt][1]);
    }

    // Epilogue: +bias, scale Q block, convert to fp16, store u32 (half2).
    const float qsc = (bn < DD) ? 0.18033688011110793f : 1.0f;   // 0.125*log2(e)
#pragma unroll
    for (int mt = 0; mt < 4; mt++) {
        const int r0 = bm + wm + mt * 16 + lr;
#pragma unroll
        for (int nt = 0; nt < 4; nt++) {
            const int cl = wn + nt * 8 + lc * 2;
            u32 v0 = pack_h2((d[mt][nt][0] + sBias[cl]) * qsc,
                             (d[mt][nt][1] + sBias[cl + 1]) * qsc);
            u32 v1 = pack_h2((d[mt][nt][2] + sBias[cl]) * qsc,
                             (d[mt][nt][3] + sBias[cl + 1]) * qsc);
            *(u32*)(C + (size_t)r0 * N3 + bn + cl) = v0;
            *(u32*)(C + (size_t)(r0 + 8) * N3 + bn + cl) = v1;
        }
    }
}

// ---------------------------------------------------------------------------
// Kernel 2: flash attention, mma.sync fp16 (m16n8k16), kv-tile 32, cp.async,
// 128 threads, q-tile 128 (2 m-tiles/warp). P relayout is pure register
// packing (C-frag pairs == A-frag); V B-frags via ldmatrix.trans.
// ---------------------------------------------------------------------------
#define AKST 72   // K/V smem row stride in halfs (144 B)
#define KV 32

__global__ __launch_bounds__(128) void attn_mma(
    const __half* __restrict__ qkv,  // [MM, N3] fp16, Q pre-scaled
    float* __restrict__ out)         // [MM, DD] f32
{
    // pool reused: fp16 K/V buffers (4608 u32) then f32 stage (8704 u32)
    __shared__ u32 pool[128 * 68];   // 34816 B
    __half* sK = (__half*)pool;                      // [2][KV][AKST]
    __half* sV = sK + 2 * KV * AKST;
    const u32 sKa = smem_u32(sK);
    const u32 sVa = smem_u32(sV);

    const int qtile = blockIdx.x;   // 0..15
    const int h     = blockIdx.y;
    const int b     = blockIdx.z;
    const int tid   = threadIdx.x;  // 0..127
    const int wid   = tid >> 5;     // 0..3
    const int lane  = tid & 31;
    const int lr    = lane >> 2;
    const int lc    = lane & 3;
    const int lm    = lane >> 3;
    const int lrw   = lane & 7;

    // staging: 32 rows x 8 segs (128 B/row); 4 threads/row; 2 segs each for K,V
    const int l_row = tid >> 2;          // 0..31
    const int l_s   = tid & 3;           // 0..3; segs l_s, l_s+4

    // ---- Q fragments resident (fp16, pre-scaled): direct u32 loads ----
    u32 qa[2][4][4];                     // [mt][kst][reg]
#pragma unroll
    for (int mt = 0; mt < 2; mt++) {
        const int row0 = qtile * 128 + wid * 32 + mt * 16;
        const __half* q0 = qkv + ((size_t)(b * LL + row0 + lr)) * N3 + h * HD;
        const __half* q1 = q0 + 8 * (size_t)N3;
#pragma unroll
        for (int kst = 0; kst < 4; kst++) {
            int kk = kst * 16;
            qa[mt][kst][0] = *(const u32*)(q0 + kk + 2 * lc);
            qa[mt][kst][1] = *(const u32*)(q1 + kk + 2 * lc);
            qa[mt][kst][2] = *(const u32*)(q0 + kk + 8 + 2 * lc);
            qa[mt][kst][3] = *(const u32*)(q1 + kk + 8 + 2 * lc);
        }
    }

    float o[2][8][4];
#pragma unroll
    for (int mt = 0; mt < 2; mt++)
#pragma unroll
        for (int dt = 0; dt < 8; dt++)
#pragma unroll
            for (int r = 0; r < 4; r++) o[mt][dt][r] = 0.f;
    float m_a[2] = {-1e30f, -1e30f}, m_b[2] = {-1e30f, -1e30f};
    float l_a[2] = {0.f, 0.f},       l_b[2] = {0.f, 0.f};

    const __half* kvbase = qkv + (size_t)b * LL * N3 + DD + h * HD;
    const __half* srcrow = kvbase + (size_t)l_row * N3;

    // prologue: tile 0 into buffer 0
#pragma unroll
    for (int i = 0; i < 2; i++) {
        int sgo = (l_s + i * 4) * 8;               // half offset of 16B seg
        u32 doff = (u32)(l_row * AKST * 2 + (l_s + i * 4) * 16);
        cpa16(sKa + doff, srcrow + sgo);
        cpa16(sVa + doff, srcrow + DD + sgo);
    }
    CP_COMMIT();

    const int NT = LL / KV;   // 64
    for (int kt = 0; kt < NT; kt++) {
        CP_WAIT0();
        __syncthreads();

        if (kt + 1 < NT) {
            const u32 bofs = (u32)(((kt + 1) & 1) * KV * AKST * 2);
            const __half* sr = srcrow + (size_t)((kt + 1) * KV) * N3;
#pragma unroll
            for (int i = 0; i < 2; i++) {
                int sgo = (l_s + i * 4) * 8;
                u32 doff = (u32)(l_row * AKST * 2 + (l_s + i * 4) * 16);
                cpa16(sKa + bofs + doff, sr + sgo);
                cpa16(sVa + bofs + doff, sr + DD + sgo);
            }
            CP_COMMIT();
        }

        const u32 bufK = sKa + (u32)((kt & 1) * KV * AKST * 2);
        const u32 bufV = sVa + (u32)((kt & 1) * KV * AKST * 2);

        // ---- S = Q K^T ----
        float s[2][4][4];
#pragma unroll
        for (int mt = 0; mt < 2; mt++)
#pragma unroll
            for (int nt = 0; nt < 4; nt++)
#pragma unroll
                for (int r = 0; r < 4; r++) s[mt][nt][r] = 0.f;

#pragma unroll
        for (int kst = 0; kst < 4; kst++) {
            const int kk = kst * 16;
            u32 bf[4][2];
            // B: m0=(nt rows, k lo) m1=(nt, k hi) m2=(nt+1, k lo) m3=(nt+1, k hi)
#pragma unroll
            for (int np = 0; np < 2; np++) {
                u32 addr = bufK + (u32)(((np * 16 + (lm >> 1) * 8 + lrw) * AKST
                                         + kk + (lm & 1) * 8) * 2);
                ldsm_x4(bf[np * 2][0], bf[np * 2][1], bf[np * 2 + 1][0], bf[np * 2 + 1][1], addr);
            }
#pragma unroll
            for (int mt = 0; mt < 2; mt++)
#pragma unroll
                for (int nt = 0; nt < 4; nt++)
                    mma_f16(s[mt][nt][0], s[mt][nt][1], s[mt][nt][2], s[mt][nt][3],
                            qa[mt][kst][0], qa[mt][kst][1], qa[mt][kst][2], qa[mt][kst][3],
                            bf[nt][0], bf[nt][1]);
        }

        // ---- online softmax; pack P directly into A-fragment half2 regs ----
        u32 pA[2][2][4];   // [mt][jt][reg]
#pragma unroll
        for (int mt = 0; mt < 2; mt++) {
            float mx_a = -1e30f, mx_b = -1e30f;
#pragma unroll
            for (int nt = 0; nt < 4; nt++) {
                mx_a = fmaxf(mx_a, fmaxf(s[mt][nt][0], s[mt][nt][1]));
                mx_b = fmaxf(mx_b, fmaxf(s[mt][nt][2], s[mt][nt][3]));
            }
            mx_a = fmaxf(mx_a, __shfl_xor_sync(0xffffffffu, mx_a, 1));
            mx_a = fmaxf(mx_a, __shfl_xor_sync(0xffffffffu, mx_a, 2));
            mx_b = fmaxf(mx_b, __shfl_xor_sync(0xffffffffu, mx_b, 1));
            mx_b = fmaxf(mx_b, __shfl_xor_sync(0xffffffffu, mx_b, 2));

            float nm_a = fmaxf(m_a[mt], mx_a);
            float nm_b = fmaxf(m_b[mt], mx_b);
            float ca = ex2(m_a[mt] - nm_a);
            float cb = ex2(m_b[mt] - nm_b);
            m_a[mt] = nm_a; m_b[mt] = nm_b;
            l_a[mt] *= ca;  l_b[mt] *= cb;
#pragma unroll
            for (int dt = 0; dt < 8; dt++) {
                o[mt][dt][0] *= ca; o[mt][dt][1] *= ca;
                o[mt][dt][2] *= cb; o[mt][dt][3] *= cb;
            }
#pragma unroll
            for (int jt = 0; jt < 2; jt++) {
                float p00 = ex2(s[mt][2 * jt][0] - m_a[mt]);
                float p01 = ex2(s[mt][2 * jt][1] - m_a[mt]);
                float p02 = ex2(s[mt][2 * jt][2] - m_b[mt]);
                float p03 = ex2(s[mt][2 * jt][3] - m_b[mt]);
                float p10 = ex2(s[mt][2 * jt + 1][0] - m_a[mt]);
                float p11 = ex2(s[mt][2 * jt + 1][1] - m_a[mt]);
                float p12 = ex2(s[mt][2 * jt + 1][2] - m_b[mt]);
                float p13 = ex2(s[mt][2 * jt + 1][3] - m_b[mt]);
                l_a[mt] += p00 + p01 + p10 + p11;
                l_b[mt] += p02 + p03 + p12 + p13;
                pA[mt][jt][0] = pack_h2(p00, p01);   // (row lr,  k 2lc,2lc+1)
                pA[mt][jt][1] = pack_h2(p02, p03);   // (row lr+8, k 2lc,2lc+1)
                pA[mt][jt][2] = pack_h2(p10, p11);   // (row lr,  k 8+2lc,..)
                pA[mt][jt][3] = pack_h2(p12, p13);   // (row lr+8, k 8+2lc,..)
            }
        }

        // ---- O += P V : V B-frags via ldmatrix.trans on row-major V ----
#pragma unroll
        for (int jt = 0; jt < 2; jt++) {
#pragma unroll
            for (int dp = 0; dp < 4; dp++) {
                u32 b00, b01, b10, b11;
                // m0=(kv lo8, d lo8) m1=(kv hi8, d lo8) m2=(kv lo8, d hi8) m3=(kv hi8, d hi8)
                u32 addr = bufV + (u32)(((jt * 16 + (lm & 1) * 8 + lrw) * AKST
                                         + dp * 16 + (lm >> 1) * 8) * 2);
                ldsm_x4_t(b00, b01, b10, b11, addr);
                const int dt0 = dp * 2, dt1 = dp * 2 + 1;
                mma_f16(o[0][dt0][0], o[0][dt0][1], o[0][dt0][2], o[0][dt0][3],
                        pA[0][jt][0], pA[0][jt][1], pA[0][jt][2], pA[0][jt][3], b00, b01);
                mma_f16(o[1][dt0][0], o[1][dt0][1], o[1][dt0][2], o[1][dt0][3],
                        pA[1][jt][0], pA[1][jt][1], pA[1][jt][2], pA[1][jt][3], b00, b01);
                mma_f16(o[0][dt1][0], o[0][dt1][1], o[0][dt1][2], o[0][dt1][3],
                        pA[0][jt][0], pA[0][jt][1], pA[0][jt][2], pA[0][jt][3], b10, b11);
                mma_f16(o[1][dt1][0], o[1][dt1][1], o[1][dt1][2], o[1][dt1][3],
                        pA[1][jt][0], pA[1][jt][1], pA[1][jt][2], pA[1][jt][3], b10, b11);
            }
        }
        __syncthreads();   // all warps done with buf kt before overwrite
    }

    // ---- final reduce + normalize ----
    float inv_a[2], inv_b[2];
#pragma unroll
    for (int mt = 0; mt < 2; mt++) {
        l_a[mt] += __shfl_xor_sync(0xffffffffu, l_a[mt], 1);
        l_a[mt] += __shfl_xor_sync(0xffffffffu, l_a[mt], 2);
        l_b[mt] += __shfl_xor_sync(0xffffffffu, l_b[mt], 1);
        l_b[mt] += __shfl_xor_sync(0xffffffffu, l_b[mt], 2);
        inv_a[mt] = 1.f / l_a[mt];
        inv_b[mt] = 1.f / l_b[mt];
    }

    // ---- stage O (128 rows x 68 f32) then coalesced store ----
    float* stage = (float*)pool;
    __syncthreads();
    {
#pragma unroll
        for (int mt = 0; mt < 2; mt++) {
            const int ra = wid * 32 + mt * 16 + lr;
            const int rb = ra + 8;
#pragma unroll
            for (int dt = 0; dt < 8; dt++) {
                float2 va, vb;
                va.x = o[mt][dt][0] * inv_a[mt]; va.y = o[mt][dt][1] * inv_a[mt];
                vb.x = o[mt][dt][2] * inv_b[mt]; vb.y = o[mt][dt][3] * inv_b[mt];
                *(float2*)&stage[ra * 68 + dt * 8 + lc * 2] = va;
                *(float2*)&stage[rb * 68 + dt * 8 + lc * 2] = vb;
            }
        }
    }
    __syncthreads();
    {
        const int cr = tid >> 4;     // 0..7
        const int cc = tid & 15;     // 0..15
#pragma unroll
        for (int pass = 0; pass < 16; pass++) {
            int row = pass * 8 + cr;
            float4 v = *(const float4*)&stage[row * 68 + cc * 4];
            *(float4*)(out + ((size_t)(b * LL + qtile * 128 + row)) * DD + h * HD + cc * 4) = v;
        }
    }
}

// ---------------------------------------------------------------------------
extern "C" void kernel_launch(void* const* d_in, const int* in_sizes, int n_in,
                              void* d_out, int out_size)
{
    const float* x    = (const float*)d_in[0];
    const float* W    = (const float*)d_in[1];
    const float* bias = (const float*)d_in[2];
    float* out = (float*)d_out;

    __half *qkvh, *xh, *wh;
    cudaGetSymbolAddress((void**)&qkvh, g_qkvh);
    cudaGetSymbolAddress((void**)&xh,   g_xh);
    cudaGetSymbolAddress((void**)&wh,   g_wh);

    const size_t n8 = ((size_t)MM * KK + (size_t)N3 * KK) / 8;   // 917504
    cvt_prepass<<<(unsigned)((n8 + 255) / 256), 256>>>(x, W, xh, wh);

    dim3 ggrid(N3 / 128, MM / 128);  // (24, 32)
    qkv_gemm_mma<<<ggrid, 256>>>(xh, wh, bias, qkvh);

    dim3 agrid(LL / 128, NH, BB);    // (16, 16, 2)
    attn_mma<<<agrid, 128>>>(qkvh, out);
}